// round 3
// baseline (speedup 1.0000x reference)
#include <cuda_runtime.h>

// BoxRenderLoss, single fused launch, R3.
//
// Boundary points = 4 edges x 25 linspace samples -> separable per-axis min:
//   min over {X0,X1}x{y_k}  = min((px-X0)^2,(px-X1)^2) + min_k (py-y_k)^2
//   min over {x_k}x{Y0,Y1}  = min((py-Y0)^2,(py-Y1)^2) + min_k (px-x_k)^2
// Nearest evenly-spaced sample found analytically (round + clamp, probe +-1).
//
// R3 changes vs R2:
//   * reciprocals 1/ow, 1/oh hoisted: 2 MUFU RCP per thread instead of 11
//     (R2 was MUFU-throughput bound: 11 RCP * rt8 matched the 8us runtime)
//   * thread granularity halved: one thread per (b, d, row, col-half),
//     5 py values per thread -> 640 blocks, ~2x occupancy.
//
// Reduction: block reduce -> one double atomicAdd per block; last block
// (self-resetting ticket) writes the scaled scalar -> graph-replayable.

#define THREADS 256

__device__ double g_sum = 0.0;          // zero-init; last block restores 0
__device__ unsigned int g_ticket = 0;   // atomicInc with wrap auto-resets

// min over k=0..24 of (p - (k*(1/24)*len + lo))^2, matching reference sampling.
// inv24len = 24/len (precomputed).
__device__ __forceinline__ float edge_min_sq(float p, float lo, float len,
                                             float inv24len) {
    const float DB = 1.0f / 24.0f;
    float tc = (p - lo) * inv24len;                // continuous nearest index
    // NaN/inf-safe clamp (len==0 -> tc inf/NaN -> k0 in range; samples coincide)
    float k0f = fminf(fmaxf(roundf(tc), 0.0f), 24.0f);
    int k0 = (int)k0f;
    float best = 3.4e38f;
#pragma unroll
    for (int dk = -1; dk <= 1; ++dk) {
        int k = min(max(k0 + dk, 0), 24);
        float s = fmaf((float)k * DB, len, lo);    // same formula as reference
        float dd = p - s;
        best = fminf(best, dd * dd);
    }
    return best;
}

__global__ __launch_bounds__(THREADS)
void box_render_loss_fused(const float4* __restrict__ boxes,
                           const float4* __restrict__ targets,
                           float* __restrict__ out,
                           int ntasks, double scale, unsigned int nblocks) {
    int t = blockIdx.x * THREADS + threadIdx.x;
    float val = 0.0f;
    if (t < ntasks) {
        int ch  = t % 2;            // column half: fi in [5*ch, 5*ch+5)
        int row = (t / 2) % 10;     // fragment row -> px
        int d   = (t / 20) & 1;     // direction: 0 = box frags vs target, 1 = swap
        int b   = t / 40;           // pair index

        float4 A = boxes[b];
        float4 T = targets[b];
        float4 F = d ? T : A;       // fragment-source box
        float4 O = d ? A : T;       // other box

        const float DF = 1.0f / 9.0f;
        float fw = F.z - F.x, fh = F.w - F.y;
        float px = fmaf((float)row * DF, fw, F.x);

        float ow = O.z - O.x, oh = O.w - O.y;
        float inv24w = 24.0f * __frcp_rn(ow);      // the only 2 MUFU ops
        float inv24h = 24.0f * __frcp_rn(oh);
        float X1 = ow + O.x;        // 1*ow + O.x, exactly as reference computes it
        float Y1 = oh + O.y;

        // x-dependent terms, hoisted across the 5 py values
        bool in_x   = (px - O.x >= 0.0f) && (O.z - px >= 0.0f);
        float dx0 = px - O.x, dx1 = px - X1;
        float vert_x = fminf(dx0 * dx0, dx1 * dx1);        // vertical edges, x part
        float dxmin  = edge_min_sq(px, O.x, ow, inv24w);   // horizontal edges, x part

        int fi0 = ch * 5;
#pragma unroll
        for (int j = 0; j < 5; ++j) {
            int fi = fi0 + j;
            float py = fmaf((float)fi * DF, fh, F.y);
            bool inside = in_x && (py - O.y >= 0.0f) && (O.w - py >= 0.0f);
            if (!inside) {
                float dymin = edge_min_sq(py, O.y, oh, inv24h);
                float dy0 = py - O.y, dy1 = py - Y1;
                float horz = fminf(dy0 * dy0, dy1 * dy1) + dxmin;
                val += fminf(vert_x + dymin, horz);
            }
        }
    }

    // block reduction: warp shuffles, then across warps via shared
    unsigned mask = 0xffffffffu;
#pragma unroll
    for (int o = 16; o > 0; o >>= 1)
        val += __shfl_down_sync(mask, val, o);

    __shared__ float ws[THREADS / 32];
    int lane = threadIdx.x & 31;
    int wid  = threadIdx.x >> 5;
    if (lane == 0) ws[wid] = val;
    __syncthreads();

    if (wid == 0) {
        float v = (lane < THREADS / 32) ? ws[lane] : 0.0f;
#pragma unroll
        for (int o = (THREADS / 32) / 2; o > 0; o >>= 1)
            v += __shfl_down_sync(mask, v, o);

        if (lane == 0) {
            atomicAdd(&g_sum, (double)v);
            __threadfence();
            // wraps back to 0 when it reaches nblocks-1 -> self-resetting
            unsigned int ticket = atomicInc(&g_ticket, nblocks - 1u);
            if (ticket == nblocks - 1u) {
                double s = g_sum;          // all adds visible (atomics + fences)
                out[0] = (float)(s * scale);
                g_sum = 0.0;               // restore for next graph replay
                __threadfence();
            }
        }
    }
}

extern "C" void kernel_launch(void* const* d_in, const int* in_sizes, int n_in,
                              void* d_out, int out_size) {
    const float4* boxes   = (const float4*)d_in[0];
    const float4* targets = (const float4*)d_in[1];
    float* out = (float*)d_out;

    int B = in_sizes[0] / 4;                 // 4096
    int ntasks = B * 40;                     // 2 dir * 10 rows * 2 col-halves
    unsigned int nblocks = (unsigned int)((ntasks + THREADS - 1) / THREADS); // 640

    double scale = 1.0 / (2.0 * (double)B * 100.0);

    box_render_loss_fused<<<nblocks, THREADS>>>(boxes, targets, out,
                                                ntasks, scale, nblocks);
}